// round 7
// baseline (speedup 1.0000x reference)
#include <cuda_runtime.h>
#include <cuda_bf16.h>

// Problem constants
#define S_TOT 8192
#define HID   2048

// Scratch (allocation-free rule: __device__ globals) — all tf32-pre-rounded f32
__device__ float g_qkv [S_TOT * 3072];      // [S][ q(2048) | k(512) | v(512) ]
__device__ float g_att [S_TOT * 2048];      // attention output (rounded)
__device__ float g_in  [S_TOT * 2048];      // rounded inputs: und rows 0..4095, gen 4096..8191
__device__ float g_wqkv[2 * 3072 * 2048];   // fused rounded [qw|kw|vw] und, gen
__device__ float g_wo  [2 * 2048 * 2048];   // rounded o_w und, gen
__device__ float g_bias[2 * 3072];          // fused bias und, gen

__device__ __forceinline__ unsigned f2t(float f) {
    unsigned u;
    asm("cvt.rna.tf32.f32 %0, %1;" : "=r"(u) : "f"(f));
    return u;
}

__device__ __forceinline__ void mma8(float c[4], const unsigned a[4], unsigned b0, unsigned b1) {
    asm volatile(
        "mma.sync.aligned.m16n8k8.row.col.f32.tf32.tf32.f32 "
        "{%0,%1,%2,%3}, {%4,%5,%6,%7}, {%8,%9}, {%0,%1,%2,%3};"
        : "+f"(c[0]), "+f"(c[1]), "+f"(c[2]), "+f"(c[3])
        : "r"(a[0]), "r"(a[1]), "r"(a[2]), "r"(a[3]), "r"(b0), "r"(b1));
}

__device__ __forceinline__ void cp16(unsigned saddr, const void* g) {
    asm volatile("cp.async.cg.shared.global [%0], [%1], 16;\n" :: "r"(saddr), "l"(g));
}

// ---------------------------------------------------------------------------
// Conversion / assembly kernels
// ---------------------------------------------------------------------------
__global__ void round_copy(float* __restrict__ dst, const float* __restrict__ src, int n4) {
    int i = blockIdx.x * blockDim.x + threadIdx.x;
    if (i >= n4) return;
    float4 v = ((const float4*)src)[i];
    ((uint4*)dst)[i] = make_uint4(f2t(v.x), f2t(v.y), f2t(v.z), f2t(v.w));
}

__global__ void assemble_qkv_w(float* __restrict__ dst,
                               const float* __restrict__ qw,
                               const float* __restrict__ kw,
                               const float* __restrict__ vw) {
    int i = blockIdx.x * blockDim.x + threadIdx.x;   // float4 index over 3072x2048
    if (i >= 3072 * 512) return;
    int pos = i * 4;
    int n = pos >> 11, k = pos & 2047;
    const float* src;
    if (n < 2048)      src = qw + (size_t)n * 2048;
    else if (n < 2560) src = kw + (size_t)(n - 2048) * 2048;
    else               src = vw + (size_t)(n - 2560) * 2048;
    float4 v = *(const float4*)(src + k);
    ((uint4*)dst)[i] = make_uint4(f2t(v.x), f2t(v.y), f2t(v.z), f2t(v.w));
}

__global__ void assemble_bias(float* __restrict__ dst,
                              const float* qb,  const float* kb,  const float* vb,
                              const float* qbg, const float* kbg, const float* vbg) {
    int i = blockIdx.x * blockDim.x + threadIdx.x;   // 0..6143
    if (i >= 6144) return;
    bool gsel = i >= 3072;
    int n = gsel ? i - 3072 : i;
    const float* q = gsel ? qbg : qb;
    const float* k = gsel ? kbg : kb;
    const float* v = gsel ? vbg : vb;
    dst[i] = (n < 2048) ? q[n] : (n < 2560) ? k[n - 2048] : v[n - 2560];
}

// ---------------------------------------------------------------------------
// Pipelined tf32 GEMM: C[m][n] = sum_k A[row(m)][k]*W[n][k] + bias[n]
// 512 threads (16 warps, 4/SMSP). CTA tile 256x128x32; warp tile 64x32 (4x4 grid).
// 4-stage cp.async ring. blockIdx.z selects und/gen parameter set.
// Columns gc >= round_from are tf32-rounded on store (pre-rounds V for attention).
// ---------------------------------------------------------------------------
#define STG_W   13824                       // words/stage: 256*36 + 128*36
#define GEMM_SMEM (4 * STG_W * 4)           // 221,184 B

__global__ __launch_bounds__(512, 1) void gemm_pipe(
    const float* __restrict__ A, size_t az, int a_off0, int a_step, int a_stride,
    const float* __restrict__ W, size_t wz,
    const float* __restrict__ bias, size_t bz,
    float* __restrict__ C, size_t cz, int ldc, int c_off0, int c_step, int c_stride,
    int round_from)
{
    extern __shared__ unsigned gsm[];
    const int tid = threadIdx.x;
    const int wid = tid >> 5, lane = tid & 31;
    const int gid = lane >> 2, tig = lane & 3;
    const int wm = (wid & 3) * 64, wn = (wid >> 2) * 32;
    const int bm = blockIdx.y * 256, bn = blockIdx.x * 128;
    const int z = blockIdx.z;

    A += (size_t)z * az;
    W += (size_t)z * wz;
    if (bias) bias += (size_t)z * bz;
    C += (size_t)z * cz;
    const int a_off = a_off0 + z * a_step;
    const int c_off = c_off0 + z * c_step;

    // loaders: thread moves 4 x 16B for A, 2 x 16B for B per stage
    const int lr  = tid >> 3;           // 0..63
    const int lc  = (tid & 7) * 4;      // 0..28
    const float* ga[4];
    const float* gw[2];
    unsigned offA[4], offB[2];
#pragma unroll
    for (int i = 0; i < 4; i++) {
        int r = lr + 64 * i;            // 0..255
        ga[i]   = A + (size_t)(a_off + (bm + r) * a_stride) * 2048 + lc;
        offA[i] = (r * 36 + lc) * 4;
    }
#pragma unroll
    for (int i = 0; i < 2; i++) {
        int r = lr + 64 * i;            // 0..127
        gw[i]   = W + (size_t)(bn + r) * 2048 + lc;
        offB[i] = (9216 + r * 36 + lc) * 4;
    }
    const unsigned sbase = (unsigned)__cvta_generic_to_shared(gsm);

#define LOADCHUNK(slot, kc) do {                                                \
    unsigned b_ = sbase + (slot) * (STG_W * 4);                                 \
    int kk_ = (kc) * 32;                                                        \
    _Pragma("unroll") for (int i_ = 0; i_ < 4; i_++) cp16(b_ + offA[i_], ga[i_] + kk_); \
    _Pragma("unroll") for (int i_ = 0; i_ < 2; i_++) cp16(b_ + offB[i_], gw[i_] + kk_); \
    asm volatile("cp.async.commit_group;\n" ::);                                \
} while (0)

    float acc[4][4][4];
#pragma unroll
    for (int i = 0; i < 4; i++)
#pragma unroll
        for (int j = 0; j < 4; j++)
#pragma unroll
            for (int c = 0; c < 4; c++) acc[i][j][c] = 0.f;

    LOADCHUNK(0, 0);
    LOADCHUNK(1, 1);
    LOADCHUNK(2, 2);

#pragma unroll 1
    for (int c = 0; c < 64; c++) {
        const int slot = c & 3;
        if (c < 62)      asm volatile("cp.async.wait_group 2;\n" ::);
        else if (c < 63) asm volatile("cp.async.wait_group 1;\n" ::);
        else             asm volatile("cp.async.wait_group 0;\n" ::);
        __syncthreads();
        if (c + 3 < 64) LOADCHUNK((c + 3) & 3, c + 3);

        const unsigned* sA = gsm + slot * STG_W;
        const unsigned* sB = sA + 9216;
#pragma unroll
        for (int ks = 0; ks < 4; ks++) {
            unsigned af[4][4], bf[4][2];
#pragma unroll
            for (int mf = 0; mf < 4; mf++) {
                const unsigned* p = &sA[(wm + mf * 16 + gid) * 36 + ks * 8 + tig];
                af[mf][0] = p[0];      af[mf][2] = p[4];
                af[mf][1] = p[8 * 36]; af[mf][3] = p[8 * 36 + 4];
            }
#pragma unroll
            for (int nf = 0; nf < 4; nf++) {
                const unsigned* p = &sB[(wn + nf * 8 + gid) * 36 + ks * 8 + tig];
                bf[nf][0] = p[0]; bf[nf][1] = p[4];
            }
#pragma unroll
            for (int mf = 0; mf < 4; mf++)
#pragma unroll
                for (int nf = 0; nf < 4; nf++)
                    mma8(acc[mf][nf], af[mf], bf[nf][0], bf[nf][1]);
        }
    }
#undef LOADCHUNK

#pragma unroll
    for (int mf = 0; mf < 4; mf++) {
#pragma unroll
        for (int nf = 0; nf < 4; nf++) {
            int gc = bn + wn + nf * 8 + tig * 2;
            float b0 = bias ? __ldg(bias + gc)     : 0.f;
            float b1 = bias ? __ldg(bias + gc + 1) : 0.f;
            int gr = bm + wm + mf * 16 + gid;
            float v00 = acc[mf][nf][0] + b0, v01 = acc[mf][nf][1] + b1;
            float v10 = acc[mf][nf][2] + b0, v11 = acc[mf][nf][3] + b1;
            if (gc >= round_from) {       // pre-round V for attention (tig*2 keeps pair together)
                v00 = __uint_as_float(f2t(v00)); v01 = __uint_as_float(f2t(v01));
                v10 = __uint_as_float(f2t(v10)); v11 = __uint_as_float(f2t(v11));
            }
            *(float2*)&C[(size_t)(c_off + gr * c_stride) * ldc + gc]       = make_float2(v00, v01);
            *(float2*)&C[(size_t)(c_off + (gr + 8) * c_stride) * ldc + gc] = make_float2(v10, v11);
        }
    }
}

// ---------------------------------------------------------------------------
// Per-head RMSNorm + RoPE, in-place on g_qkv; outputs tf32-ROUNDED (consumed
// raw by attention mma). One warp per (token, head).
// ---------------------------------------------------------------------------
__global__ __launch_bounds__(256) void norm_rope(
    float* __restrict__ qkv,
    const float* __restrict__ cosp, const float* __restrict__ sinp,
    const float* __restrict__ qn, const float* __restrict__ qng,
    const float* __restrict__ kn, const float* __restrict__ kng)
{
    int task = blockIdx.x * 8 + (threadIdx.x >> 5);
    int lane = threadIdx.x & 31;
    int s = task / 20, j = task % 20;
    bool und = (s & 1) == 0;
    const float* w;
    int off;
    if (j < 16) { off = j * 128;               w = und ? qn : qng; }
    else        { off = 2048 + (j - 16) * 128; w = und ? kn : kng; }

    float* p = qkv + (size_t)s * 3072 + off;
    float x0 = p[lane], x1 = p[lane + 32], x2 = p[lane + 64], x3 = p[lane + 96];
    float ss = x0 * x0 + x1 * x1 + x2 * x2 + x3 * x3;
#pragma unroll
    for (int d = 16; d; d >>= 1) ss += __shfl_xor_sync(0xffffffffu, ss, d);
    float r = rsqrtf(ss * (1.0f / 128.0f) + 1e-6f);
    x0 = x0 * r * w[lane];      x1 = x1 * r * w[lane + 32];
    x2 = x2 * r * w[lane + 64]; x3 = x3 * r * w[lane + 96];

    const float* cs = cosp + (size_t)s * 128;
    const float* sn = sinp + (size_t)s * 128;
    float c0 = cs[lane], c1 = cs[lane + 32], c2 = cs[lane + 64], c3 = cs[lane + 96];
    float s0 = sn[lane], s1 = sn[lane + 32], s2 = sn[lane + 64], s3 = sn[lane + 96];

    p[lane]      = __uint_as_float(f2t(x0 * c0 - x2 * s0));
    p[lane + 32] = __uint_as_float(f2t(x1 * c1 - x3 * s1));
    p[lane + 64] = __uint_as_float(f2t(x2 * c2 + x0 * s2));
    p[lane + 96] = __uint_as_float(f2t(x3 * c3 + x1 * s3));
}

// ---------------------------------------------------------------------------
// Causal GQA flash attention (tf32 mma). K/V pre-rounded -> raw cp.async fill.
// Scores scaled AFTER the QK mma (softmax-invariant reordering).
// ---------------------------------------------------------------------------
#define SK_STR 132
#define SV_STR 136
#define SP_STR 68
#define KV_W   (64 * SK_STR + 64 * SV_STR)   // 17152 words
#define ATT_SMEM ((KV_W + 8 * 16 * SP_STR) * 4)

__global__ __launch_bounds__(256, 1) void attn_kernel(
    const float* __restrict__ qkv, float* __restrict__ outp)
{
    extern __shared__ unsigned sm[];
    unsigned* sK = sm;
    unsigned* sV = sm + 64 * SK_STR;
    float* sP = (float*)(sm + KV_W);

    const int qt = blockIdx.x, hkv = blockIdx.y, b = blockIdx.z;
    const int tid = threadIdx.x, wid = tid >> 5, lane = tid & 31;
    const int gid = lane >> 2, tig = lane & 3;
    const int g = wid >> 1;
    const int h = hkv * 4 + g;
    const int q0 = qt * 32;
    const int qrow = q0 + (wid & 1) * 16 + gid;
    const int trow = b * 512 + qrow;
    const float scale = 0.08838834764831845f;  // applied to scores post-mma

    // Q fragments: pre-rounded by norm_rope, load raw
    unsigned qa[16][4];
    {
        const float* qp  = qkv + (size_t)trow * 3072 + h * 128;
        const float* qp8 = qp + 8 * 3072;
#pragma unroll
        for (int kf = 0; kf < 16; kf++) {
            qa[kf][0] = __float_as_uint(qp [kf * 8 + tig]);
            qa[kf][2] = __float_as_uint(qp [kf * 8 + tig + 4]);
            qa[kf][1] = __float_as_uint(qp8[kf * 8 + tig]);
            qa[kf][3] = __float_as_uint(qp8[kf * 8 + tig + 4]);
        }
    }

    // cp.async loader mapping: 4 threads/row, 8 chunks each for K and V
    const unsigned sb = (unsigned)__cvta_generic_to_shared(sm);
    const int krow = tid >> 2;             // 0..63
    const int kcb  = (tid & 3) * 32;       // word col base

    float o[16][4];
#pragma unroll
    for (int i = 0; i < 16; i++)
#pragma unroll
        for (int c = 0; c < 4; c++) o[i][c] = 0.f;
    float m0 = -1e30f, m1 = -1e30f, l0 = 0.f, l1 = 0.f;
    float* myP = sP + wid * 16 * SP_STR;
    const int ntiles = (q0 >> 6) + 1;

#pragma unroll 1
    for (int j = 0; j < ntiles; j++) {
        int c0 = j * 64;
        __syncthreads();
        {
            const float* kb = qkv + (size_t)(b * 512 + c0 + krow) * 3072 + 2048 + hkv * 128 + kcb;
            const float* vb = kb + 512;
#pragma unroll
            for (int t = 0; t < 8; t++) {
                cp16(sb + (krow * SK_STR + kcb + t * 4) * 4, kb + t * 4);
                cp16(sb + (64 * SK_STR + krow * SV_STR + kcb + t * 4) * 4, vb + t * 4);
            }
            asm volatile("cp.async.commit_group;\n" ::);
            asm volatile("cp.async.wait_group 0;\n" ::);
        }
        __syncthreads();

        float s[8][4];
#pragma unroll
        for (int nf = 0; nf < 8; nf++)
#pragma unroll
            for (int c = 0; c < 4; c++) s[nf][c] = 0.f;

#pragma unroll
        for (int kf = 0; kf < 16; kf++) {
#pragma unroll
            for (int nf = 0; nf < 8; nf++) {
                unsigned b0 = sK[(nf * 8 + gid) * SK_STR + kf * 8 + tig];
                unsigned b1 = sK[(nf * 8 + gid) * SK_STR + kf * 8 + tig + 4];
                mma8(s[nf], qa[kf], b0, b1);
            }
        }

#pragma unroll
        for (int nf = 0; nf < 8; nf++)
#pragma unroll
            for (int c = 0; c < 4; c++) s[nf][c] *= scale;

        if (j == ntiles - 1) {
#pragma unroll
            for (int nf = 0; nf < 8; nf++) {
                int col = c0 + nf * 8 + tig * 2;
                if (col     > qrow)     s[nf][0] = -1e30f;
                if (col + 1 > qrow)     s[nf][1] = -1e30f;
                if (col     > qrow + 8) s[nf][2] = -1e30f;
                if (col + 1 > qrow + 8) s[nf][3] = -1e30f;
            }
        }

        float mj0 = -1e30f, mj1 = -1e30f;
#pragma unroll
        for (int nf = 0; nf < 8; nf++) {
            mj0 = fmaxf(mj0, fmaxf(s[nf][0], s[nf][1]));
            mj1 = fmaxf(mj1, fmaxf(s[nf][2], s[nf][3]));
        }
        mj0 = fmaxf(mj0, __shfl_xor_sync(0xffffffffu, mj0, 1));
        mj0 = fmaxf(mj0, __shfl_xor_sync(0xffffffffu, mj0, 2));
        mj1 = fmaxf(mj1, __shfl_xor_sync(0xffffffffu, mj1, 1));
        mj1 = fmaxf(mj1, __shfl_xor_sync(0xffffffffu, mj1, 2));

        float mn0 = fmaxf(m0, mj0), mn1 = fmaxf(m1, mj1);
        float f0 = __expf(m0 - mn0), f1 = __expf(m1 - mn1);
        m0 = mn0; m1 = mn1;
        l0 *= f0; l1 *= f1;
#pragma unroll
        for (int nf = 0; nf < 16; nf++) {
            o[nf][0] *= f0; o[nf][1] *= f0;
            o[nf][2] *= f1; o[nf][3] *= f1;
        }
#pragma unroll
        for (int nf = 0; nf < 8; nf++) {
            float p0 = __expf(s[nf][0] - m0), p1 = __expf(s[nf][1] - m0);
            float p2 = __expf(s[nf][2] - m1), p3 = __expf(s[nf][3] - m1);
            l0 += p0 + p1; l1 += p2 + p3;
            *(float2*)&myP[gid * SP_STR + nf * 8 + tig * 2]       = make_float2(p0, p1);
            *(float2*)&myP[(gid + 8) * SP_STR + nf * 8 + tig * 2] = make_float2(p2, p3);
        }
        __syncwarp();
#pragma unroll
        for (int kf = 0; kf < 8; kf++) {
            unsigned a[4];
            a[0] = f2t(myP[gid * SP_STR + kf * 8 + tig]);
            a[2] = f2t(myP[gid * SP_STR + kf * 8 + tig + 4]);
            a[1] = f2t(myP[(gid + 8) * SP_STR + kf * 8 + tig]);
            a[3] = f2t(myP[(gid + 8) * SP_STR + kf * 8 + tig + 4]);
#pragma unroll
            for (int nf = 0; nf < 16; nf++) {
                unsigned b0 = sV[(kf * 8 + tig) * SV_STR + nf * 8 + gid];
                unsigned b1 = sV[(kf * 8 + tig + 4) * SV_STR + nf * 8 + gid];
                mma8(o[nf], a, b0, b1);
            }
        }
        __syncwarp();
    }

    float L0 = l0 + __shfl_xor_sync(0xffffffffu, l0, 1);
    L0 += __shfl_xor_sync(0xffffffffu, L0, 2);
    float L1 = l1 + __shfl_xor_sync(0xffffffffu, l1, 1);
    L1 += __shfl_xor_sync(0xffffffffu, L1, 2);
    float inv0 = 1.f / L0, inv1 = 1.f / L1;

    // tf32-rounded output for the o-projection
    float* op  = outp + (size_t)trow * 2048 + h * 128;
    float* op8 = op + 8 * 2048;
#pragma unroll
    for (int nf = 0; nf < 16; nf++) {
        int d = nf * 8 + tig * 2;
        *(uint2*)&op[d]  = make_uint2(f2t(o[nf][0] * inv0), f2t(o[nf][1] * inv0));
        *(uint2*)&op8[d] = make_uint2(f2t(o[nf][2] * inv1), f2t(o[nf][3] * inv1));
    }
}

// ---------------------------------------------------------------------------
extern "C" void kernel_launch(void* const* d_in, const int* in_sizes, int n_in,
                              void* d_out, int out_size)
{
    const float* und  = (const float*)d_in[0];
    const float* gen  = (const float*)d_in[1];
    const float* q_w  = (const float*)d_in[4];
    const float* q_b  = (const float*)d_in[5];
    const float* k_w  = (const float*)d_in[6];
    const float* k_b  = (const float*)d_in[7];
    const float* v_w  = (const float*)d_in[8];
    const float* v_b  = (const float*)d_in[9];
    const float* o_w  = (const float*)d_in[10];
    const float* q_wg = (const float*)d_in[11];
    const float* q_bg = (const float*)d_in[12];
    const float* k_wg = (const float*)d_in[13];
    const float* k_bg = (const float*)d_in[14];
    const float* v_wg = (const float*)d_in[15];
    const float* v_bg = (const float*)d_in[16];
    const float* o_wg = (const float*)d_in[17];
    const float* qn   = (const float*)d_in[18];
    const float* kn   = (const float*)d_in[19];
    const float* qng  = (const float*)d_in[20];
    const float* kng  = (const float*)d_in[21];
    const float* cosp = (const float*)d_in[22];
    const float* sinp = (const float*)d_in[23];
    float* out = (float*)d_out;

    float *qkv, *att, *inb, *wqkv, *wo, *bias;
    cudaGetSymbolAddress((void**)&qkv,  g_qkv);
    cudaGetSymbolAddress((void**)&att,  g_att);
    cudaGetSymbolAddress((void**)&inb,  g_in);
    cudaGetSymbolAddress((void**)&wqkv, g_wqkv);
    cudaGetSymbolAddress((void**)&wo,   g_wo);
    cudaGetSymbolAddress((void**)&bias, g_bias);

    cudaFuncSetAttribute(gemm_pipe,   cudaFuncAttributeMaxDynamicSharedMemorySize, GEMM_SMEM);
    cudaFuncSetAttribute(attn_kernel, cudaFuncAttributeMaxDynamicSharedMemorySize, ATT_SMEM);

    // Pre-round everything to tf32 (numerics identical to in-GEMM rounding)
    round_copy<<<8192, 256>>>(inb,                 und,  4096 * 512);
    round_copy<<<8192, 256>>>(inb + 4096 * 2048,   gen,  4096 * 512);
    round_copy<<<4096, 256>>>(wo,                  o_w,  2048 * 512);
    round_copy<<<4096, 256>>>(wo + 2048 * 2048,    o_wg, 2048 * 512);
    assemble_qkv_w<<<6144, 256>>>(wqkv,               q_w,  k_w,  v_w);
    assemble_qkv_w<<<6144, 256>>>(wqkv + 3072 * 2048, q_wg, k_wg, v_wg);
    assemble_bias<<<24, 256>>>(bias, q_b, k_b, v_b, q_bg, k_bg, v_bg);

    // Fused QKV projections, und+gen in one launch (z): und -> even tokens, gen -> odd.
    // V columns (>=2560) pre-rounded for attention.
    gemm_pipe<<<dim3(24, 16, 2), 512, GEMM_SMEM>>>(
        inb, (size_t)4096 * 2048, 0, 0, 1,
        wqkv, (size_t)3072 * 2048,
        bias, 3072,
        qkv, 0, 3072, 0, 1, 2,
        2560);

    // RMSNorm + RoPE (rounds q,k outputs)
    norm_rope<<<20480, 256>>>(qkv, cosp, sinp, qn, qng, kn, kng);

    // Flash attention (writes rounded output)
    attn_kernel<<<dim3(16, 4, 16), 256, ATT_SMEM>>>(qkv, att);

    // Output projections, und+gen in one launch (z)
    gemm_pipe<<<dim3(16, 16, 2), 512, GEMM_SMEM>>>(
        att, 0, 0, 1, 2,
        wo, (size_t)2048 * 2048,
        nullptr, 0,
        out, (size_t)4096 * 2048, 2048, 0, 0, 1,
        1 << 30);
}

// round 9
// speedup vs baseline: 1.6332x; 1.6332x over previous
#include <cuda_runtime.h>
#include <cuda_bf16.h>

// Problem constants
#define S_TOT 8192
#define HID   2048

// Scratch (allocation-free rule: __device__ globals) — all tf32-pre-rounded f32
__device__ float g_qkv [S_TOT * 3072];      // [S][ q(2048) | k(512) | v(512) ]
__device__ float g_att [S_TOT * 2048];      // attention output (rounded)
__device__ float g_in  [S_TOT * 2048];      // rounded inputs: und rows 0..4095, gen 4096..8191
__device__ float g_wqkv[2 * 3072 * 2048];   // fused rounded [qw|kw|vw] und, gen
__device__ float g_wo  [2 * 2048 * 2048];   // rounded o_w und, gen
__device__ float g_bias[2 * 3072];          // fused bias und, gen

__device__ __forceinline__ unsigned f2t(float f) {
    unsigned u;
    asm("cvt.rna.tf32.f32 %0, %1;" : "=r"(u) : "f"(f));
    return u;
}

__device__ __forceinline__ void mma8(float c[4], const unsigned a[4], unsigned b0, unsigned b1) {
    asm volatile(
        "mma.sync.aligned.m16n8k8.row.col.f32.tf32.tf32.f32 "
        "{%0,%1,%2,%3}, {%4,%5,%6,%7}, {%8,%9}, {%0,%1,%2,%3};"
        : "+f"(c[0]), "+f"(c[1]), "+f"(c[2]), "+f"(c[3])
        : "r"(a[0]), "r"(a[1]), "r"(a[2]), "r"(a[3]), "r"(b0), "r"(b1));
}

__device__ __forceinline__ void cp16(unsigned saddr, const void* g) {
    asm volatile("cp.async.cg.shared.global [%0], [%1], 16;\n" :: "r"(saddr), "l"(g));
}

// ---------------------------------------------------------------------------
// Conversion / assembly kernels
// ---------------------------------------------------------------------------
__global__ void round_copy(float* __restrict__ dst, const float* __restrict__ src, int n4) {
    int i = blockIdx.x * blockDim.x + threadIdx.x;
    if (i >= n4) return;
    float4 v = ((const float4*)src)[i];
    ((uint4*)dst)[i] = make_uint4(f2t(v.x), f2t(v.y), f2t(v.z), f2t(v.w));
}

__global__ void assemble_qkv_w(float* __restrict__ dst,
                               const float* __restrict__ qw,
                               const float* __restrict__ kw,
                               const float* __restrict__ vw) {
    int i = blockIdx.x * blockDim.x + threadIdx.x;   // float4 index over 3072x2048
    if (i >= 3072 * 512) return;
    int pos = i * 4;
    int n = pos >> 11, k = pos & 2047;
    const float* src;
    if (n < 2048)      src = qw + (size_t)n * 2048;
    else if (n < 2560) src = kw + (size_t)(n - 2048) * 2048;
    else               src = vw + (size_t)(n - 2560) * 2048;
    float4 v = *(const float4*)(src + k);
    ((uint4*)dst)[i] = make_uint4(f2t(v.x), f2t(v.y), f2t(v.z), f2t(v.w));
}

__global__ void assemble_bias(float* __restrict__ dst,
                              const float* qb,  const float* kb,  const float* vb,
                              const float* qbg, const float* kbg, const float* vbg) {
    int i = blockIdx.x * blockDim.x + threadIdx.x;   // 0..6143
    if (i >= 6144) return;
    bool gsel = i >= 3072;
    int n = gsel ? i - 3072 : i;
    const float* q = gsel ? qbg : qb;
    const float* k = gsel ? kbg : kb;
    const float* v = gsel ? vbg : vb;
    dst[i] = (n < 2048) ? q[n] : (n < 2560) ? k[n - 2048] : v[n - 2560];
}

// ---------------------------------------------------------------------------
// Pipelined tf32 GEMM: C[m][n] = sum_k A[row(m)][k]*W[n][k] + bias[n]
// 256 threads, 8 warps (4m x 2n), warp tile 64x64. CTA tile 256x128, K-chunk 64,
// 2-stage ring (209KB smem). blockIdx.z selects und/gen parameter set.
// Columns gc >= round_from are tf32-rounded on store (pre-rounds V for attention).
// ---------------------------------------------------------------------------
#define ROW_W   68                           // words per K=64 row (stride 68: conflict-free frags)
#define STG_W   ((256 + 128) * ROW_W)        // 26112 words per stage
#define GEMM_SMEM (2 * STG_W * 4)            // 208,896 B

__global__ __launch_bounds__(256, 1) void gemm_pipe(
    const float* __restrict__ A, size_t az, int a_off0, int a_step, int a_stride,
    const float* __restrict__ W, size_t wz,
    const float* __restrict__ bias, size_t bz,
    float* __restrict__ C, size_t cz, int ldc, int c_off0, int c_step, int c_stride,
    int round_from)
{
    extern __shared__ unsigned gsm[];
    const int tid = threadIdx.x;
    const int wid = tid >> 5, lane = tid & 31;
    const int gid = lane >> 2, tig = lane & 3;
    const int wm = (wid & 3) * 64, wn = (wid >> 2) * 64;
    const int bm = blockIdx.y * 256, bn = blockIdx.x * 128;
    const int z = blockIdx.z;

    A += (size_t)z * az;
    W += (size_t)z * wz;
    if (bias) bias += (size_t)z * bz;
    C += (size_t)z * cz;
    const int a_off = a_off0 + z * a_step;
    const int c_off = c_off0 + z * c_step;

    // loaders: thread moves 16 x 16B for A, 8 x 16B for B per stage (two col-halves)
    const int lr  = tid >> 3;           // 0..31
    const int lc  = (tid & 7) * 4;      // word col in first 32-half
    const float* ga[8];
    const float* gw[4];
    unsigned offA[8], offB[4];
#pragma unroll
    for (int i = 0; i < 8; i++) {
        int r = lr + 32 * i;            // 0..255
        ga[i]   = A + (size_t)(a_off + (bm + r) * a_stride) * 2048 + lc;
        offA[i] = (r * ROW_W + lc) * 4;
    }
#pragma unroll
    for (int i = 0; i < 4; i++) {
        int r = lr + 32 * i;            // 0..127
        gw[i]   = W + (size_t)(bn + r) * 2048 + lc;
        offB[i] = ((256 + r) * ROW_W + lc) * 4;
    }
    const unsigned sbase = (unsigned)__cvta_generic_to_shared(gsm);

#define LOADCHUNK(slot, kc) do {                                                       \
    unsigned b_ = sbase + (slot) * (STG_W * 4);                                        \
    int kk_ = (kc) * 64;                                                               \
    _Pragma("unroll") for (int i_ = 0; i_ < 8; i_++) {                                 \
        cp16(b_ + offA[i_],       ga[i_] + kk_);                                       \
        cp16(b_ + offA[i_] + 128, ga[i_] + kk_ + 32);                                  \
    }                                                                                  \
    _Pragma("unroll") for (int i_ = 0; i_ < 4; i_++) {                                 \
        cp16(b_ + offB[i_],       gw[i_] + kk_);                                       \
        cp16(b_ + offB[i_] + 128, gw[i_] + kk_ + 32);                                  \
    }                                                                                  \
    asm volatile("cp.async.commit_group;\n" ::);                                       \
} while (0)

    float acc[4][8][4];
#pragma unroll
    for (int i = 0; i < 4; i++)
#pragma unroll
        for (int j = 0; j < 8; j++)
#pragma unroll
            for (int c = 0; c < 4; c++) acc[i][j][c] = 0.f;

    LOADCHUNK(0, 0);
    LOADCHUNK(1, 1);

#pragma unroll 1
    for (int c = 0; c < 32; c++) {
        const int slot = c & 1;
        if (c < 31) asm volatile("cp.async.wait_group 1;\n" ::);
        else        asm volatile("cp.async.wait_group 0;\n" ::);
        __syncthreads();

        const unsigned* sA = gsm + slot * STG_W;
        const unsigned* sB = sA + 256 * ROW_W;
#pragma unroll
        for (int ks = 0; ks < 8; ks++) {
            unsigned af[4][4], bf[8][2];
#pragma unroll
            for (int mf = 0; mf < 4; mf++) {
                const unsigned* p = &sA[(wm + mf * 16 + gid) * ROW_W + ks * 8 + tig];
                af[mf][0] = p[0];          af[mf][2] = p[4];
                af[mf][1] = p[8 * ROW_W];  af[mf][3] = p[8 * ROW_W + 4];
            }
#pragma unroll
            for (int nf = 0; nf < 8; nf++) {
                const unsigned* p = &sB[(wn + nf * 8 + gid) * ROW_W + ks * 8 + tig];
                bf[nf][0] = p[0]; bf[nf][1] = p[4];
            }
#pragma unroll
            for (int mf = 0; mf < 4; mf++)
#pragma unroll
                for (int nf = 0; nf < 8; nf++)
                    mma8(acc[mf][nf], af[mf], bf[nf][0], bf[nf][1]);
        }

        if (c + 2 < 32) {
            __syncthreads();               // all warps done reading this slot
            LOADCHUNK(slot, c + 2);        // overlaps compute of chunk c+1
        }
    }
#undef LOADCHUNK

#pragma unroll
    for (int mf = 0; mf < 4; mf++) {
#pragma unroll
        for (int nf = 0; nf < 8; nf++) {
            int gc = bn + wn + nf * 8 + tig * 2;
            float b0 = bias ? __ldg(bias + gc)     : 0.f;
            float b1 = bias ? __ldg(bias + gc + 1) : 0.f;
            int gr = bm + wm + mf * 16 + gid;
            float v00 = acc[mf][nf][0] + b0, v01 = acc[mf][nf][1] + b1;
            float v10 = acc[mf][nf][2] + b0, v11 = acc[mf][nf][3] + b1;
            if (gc >= round_from) {
                v00 = __uint_as_float(f2t(v00)); v01 = __uint_as_float(f2t(v01));
                v10 = __uint_as_float(f2t(v10)); v11 = __uint_as_float(f2t(v11));
            }
            *(float2*)&C[(size_t)(c_off + gr * c_stride) * ldc + gc]       = make_float2(v00, v01);
            *(float2*)&C[(size_t)(c_off + (gr + 8) * c_stride) * ldc + gc] = make_float2(v10, v11);
        }
    }
}

// ---------------------------------------------------------------------------
// Per-head RMSNorm + RoPE, in-place on g_qkv; outputs tf32-ROUNDED.
// ---------------------------------------------------------------------------
__global__ __launch_bounds__(256) void norm_rope(
    float* __restrict__ qkv,
    const float* __restrict__ cosp, const float* __restrict__ sinp,
    const float* __restrict__ qn, const float* __restrict__ qng,
    const float* __restrict__ kn, const float* __restrict__ kng)
{
    int task = blockIdx.x * 8 + (threadIdx.x >> 5);
    int lane = threadIdx.x & 31;
    int s = task / 20, j = task % 20;
    bool und = (s & 1) == 0;
    const float* w;
    int off;
    if (j < 16) { off = j * 128;               w = und ? qn : qng; }
    else        { off = 2048 + (j - 16) * 128; w = und ? kn : kng; }

    float* p = qkv + (size_t)s * 3072 + off;
    float x0 = p[lane], x1 = p[lane + 32], x2 = p[lane + 64], x3 = p[lane + 96];
    float ss = x0 * x0 + x1 * x1 + x2 * x2 + x3 * x3;
#pragma unroll
    for (int d = 16; d; d >>= 1) ss += __shfl_xor_sync(0xffffffffu, ss, d);
    float r = rsqrtf(ss * (1.0f / 128.0f) + 1e-6f);
    x0 = x0 * r * w[lane];      x1 = x1 * r * w[lane + 32];
    x2 = x2 * r * w[lane + 64]; x3 = x3 * r * w[lane + 96];

    const float* cs = cosp + (size_t)s * 128;
    const float* sn = sinp + (size_t)s * 128;
    float c0 = cs[lane], c1 = cs[lane + 32], c2 = cs[lane + 64], c3 = cs[lane + 96];
    float s0 = sn[lane], s1 = sn[lane + 32], s2 = sn[lane + 64], s3 = sn[lane + 96];

    p[lane]      = __uint_as_float(f2t(x0 * c0 - x2 * s0));
    p[lane + 32] = __uint_as_float(f2t(x1 * c1 - x3 * s1));
    p[lane + 64] = __uint_as_float(f2t(x2 * c2 + x0 * s2));
    p[lane + 96] = __uint_as_float(f2t(x3 * c3 + x1 * s3));
}

// ---------------------------------------------------------------------------
// Causal GQA flash attention (tf32 mma). K/V pre-rounded -> raw cp.async fill.
// ---------------------------------------------------------------------------
#define SK_STR 132
#define SV_STR 136
#define SP_STR 68
#define KV_W   (64 * SK_STR + 64 * SV_STR)
#define ATT_SMEM ((KV_W + 8 * 16 * SP_STR) * 4)

__global__ __launch_bounds__(256, 1) void attn_kernel(
    const float* __restrict__ qkv, float* __restrict__ outp)
{
    extern __shared__ unsigned sm[];
    unsigned* sK = sm;
    unsigned* sV = sm + 64 * SK_STR;
    float* sP = (float*)(sm + KV_W);

    const int qt = blockIdx.x, hkv = blockIdx.y, b = blockIdx.z;
    const int tid = threadIdx.x, wid = tid >> 5, lane = tid & 31;
    const int gid = lane >> 2, tig = lane & 3;
    const int g = wid >> 1;
    const int h = hkv * 4 + g;
    const int q0 = qt * 32;
    const int qrow = q0 + (wid & 1) * 16 + gid;
    const int trow = b * 512 + qrow;
    const float scale = 0.08838834764831845f;

    unsigned qa[16][4];
    {
        const float* qp  = qkv + (size_t)trow * 3072 + h * 128;
        const float* qp8 = qp + 8 * 3072;
#pragma unroll
        for (int kf = 0; kf < 16; kf++) {
            qa[kf][0] = __float_as_uint(qp [kf * 8 + tig]);
            qa[kf][2] = __float_as_uint(qp [kf * 8 + tig + 4]);
            qa[kf][1] = __float_as_uint(qp8[kf * 8 + tig]);
            qa[kf][3] = __float_as_uint(qp8[kf * 8 + tig + 4]);
        }
    }

    const unsigned sb = (unsigned)__cvta_generic_to_shared(sm);
    const int krow = tid >> 2;
    const int kcb  = (tid & 3) * 32;

    float o[16][4];
#pragma unroll
    for (int i = 0; i < 16; i++)
#pragma unroll
        for (int c = 0; c < 4; c++) o[i][c] = 0.f;
    float m0 = -1e30f, m1 = -1e30f, l0 = 0.f, l1 = 0.f;
    float* myP = sP + wid * 16 * SP_STR;
    const int ntiles = (q0 >> 6) + 1;

#pragma unroll 1
    for (int j = 0; j < ntiles; j++) {
        int c0 = j * 64;
        __syncthreads();
        {
            const float* kb = qkv + (size_t)(b * 512 + c0 + krow) * 3072 + 2048 + hkv * 128 + kcb;
            const float* vb = kb + 512;
#pragma unroll
            for (int t = 0; t < 8; t++) {
                cp16(sb + (krow * SK_STR + kcb + t * 4) * 4, kb + t * 4);
                cp16(sb + (64 * SK_STR + krow * SV_STR + kcb + t * 4) * 4, vb + t * 4);
            }
            asm volatile("cp.async.commit_group;\n" ::);
            asm volatile("cp.async.wait_group 0;\n" ::);
        }
        __syncthreads();

        float s[8][4];
#pragma unroll
        for (int nf = 0; nf < 8; nf++)
#pragma unroll
            for (int c = 0; c < 4; c++) s[nf][c] = 0.f;

#pragma unroll
        for (int kf = 0; kf < 16; kf++) {
#pragma unroll
            for (int nf = 0; nf < 8; nf++) {
                unsigned b0 = sK[(nf * 8 + gid) * SK_STR + kf * 8 + tig];
                unsigned b1 = sK[(nf * 8 + gid) * SK_STR + kf * 8 + tig + 4];
                mma8(s[nf], qa[kf], b0, b1);
            }
        }

#pragma unroll
        for (int nf = 0; nf < 8; nf++)
#pragma unroll
            for (int c = 0; c < 4; c++) s[nf][c] *= scale;

        if (j == ntiles - 1) {
#pragma unroll
            for (int nf = 0; nf < 8; nf++) {
                int col = c0 + nf * 8 + tig * 2;
                if (col     > qrow)     s[nf][0] = -1e30f;
                if (col + 1 > qrow)     s[nf][1] = -1e30f;
                if (col     > qrow + 8) s[nf][2] = -1e30f;
                if (col + 1 > qrow + 8) s[nf][3] = -1e30f;
            }
        }

        float mj0 = -1e30f, mj1 = -1e30f;
#pragma unroll
        for (int nf = 0; nf < 8; nf++) {
            mj0 = fmaxf(mj0, fmaxf(s[nf][0], s[nf][1]));
            mj1 = fmaxf(mj1, fmaxf(s[nf][2], s[nf][3]));
        }
        mj0 = fmaxf(mj0, __shfl_xor_sync(0xffffffffu, mj0, 1));
        mj0 = fmaxf(mj0, __shfl_xor_sync(0xffffffffu, mj0, 2));
        mj1 = fmaxf(mj1, __shfl_xor_sync(0xffffffffu, mj1, 1));
        mj1 = fmaxf(mj1, __shfl_xor_sync(0xffffffffu, mj1, 2));

        float mn0 = fmaxf(m0, mj0), mn1 = fmaxf(m1, mj1);
        float f0 = __expf(m0 - mn0), f1 = __expf(m1 - mn1);
        m0 = mn0; m1 = mn1;
        l0 *= f0; l1 *= f1;
#pragma unroll
        for (int nf = 0; nf < 16; nf++) {
            o[nf][0] *= f0; o[nf][1] *= f0;
            o[nf][2] *= f1; o[nf][3] *= f1;
        }
#pragma unroll
        for (int nf = 0; nf < 8; nf++) {
            float p0 = __expf(s[nf][0] - m0), p1 = __expf(s[nf][1] - m0);
            float p2 = __expf(s[nf][2] - m1), p3 = __expf(s[nf][3] - m1);
            l0 += p0 + p1; l1 += p2 + p3;
            *(float2*)&myP[gid * SP_STR + nf * 8 + tig * 2]       = make_float2(p0, p1);
            *(float2*)&myP[(gid + 8) * SP_STR + nf * 8 + tig * 2] = make_float2(p2, p3);
        }
        __syncwarp();
#pragma unroll
        for (int kf = 0; kf < 8; kf++) {
            unsigned a[4];
            a[0] = f2t(myP[gid * SP_STR + kf * 8 + tig]);
            a[2] = f2t(myP[gid * SP_STR + kf * 8 + tig + 4]);
            a[1] = f2t(myP[(gid + 8) * SP_STR + kf * 8 + tig]);
            a[3] = f2t(myP[(gid + 8) * SP_STR + kf * 8 + tig + 4]);
#pragma unroll
            for (int nf = 0; nf < 16; nf++) {
                unsigned b0 = sV[(kf * 8 + tig) * SV_STR + nf * 8 + gid];
                unsigned b1 = sV[(kf * 8 + tig + 4) * SV_STR + nf * 8 + gid];
                mma8(o[nf], a, b0, b1);
            }
        }
        __syncwarp();
    }

    float L0 = l0 + __shfl_xor_sync(0xffffffffu, l0, 1);
    L0 += __shfl_xor_sync(0xffffffffu, L0, 2);
    float L1 = l1 + __shfl_xor_sync(0xffffffffu, l1, 1);
    L1 += __shfl_xor_sync(0xffffffffu, L1, 2);
    float inv0 = 1.f / L0, inv1 = 1.f / L1;

    float* op  = outp + (size_t)trow * 2048 + h * 128;
    float* op8 = op + 8 * 2048;
#pragma unroll
    for (int nf = 0; nf < 16; nf++) {
        int d = nf * 8 + tig * 2;
        *(uint2*)&op[d]  = make_uint2(f2t(o[nf][0] * inv0), f2t(o[nf][1] * inv0));
        *(uint2*)&op8[d] = make_uint2(f2t(o[nf][2] * inv1), f2t(o[nf][3] * inv1));
    }
}

// ---------------------------------------------------------------------------
extern "C" void kernel_launch(void* const* d_in, const int* in_sizes, int n_in,
                              void* d_out, int out_size)
{
    const float* und  = (const float*)d_in[0];
    const float* gen  = (const float*)d_in[1];
    const float* q_w  = (const float*)d_in[4];
    const float* q_b  = (const float*)d_in[5];
    const float* k_w  = (const float*)d_in[6];
    const float* k_b  = (const float*)d_in[7];
    const float* v_w  = (const float*)d_in[8];
    const float* v_b  = (const float*)d_in[9];
    const float* o_w  = (const float*)d_in[10];
    const float* q_wg = (const float*)d_in[11];
    const float* q_bg = (const float*)d_in[12];
    const float* k_wg = (const float*)d_in[13];
    const float* k_bg = (const float*)d_in[14];
    const float* v_wg = (const float*)d_in[15];
    const float* v_bg = (const float*)d_in[16];
    const float* o_wg = (const float*)d_in[17];
    const float* qn   = (const float*)d_in[18];
    const float* kn   = (const float*)d_in[19];
    const float* qng  = (const float*)d_in[20];
    const float* kng  = (const float*)d_in[21];
    const float* cosp = (const float*)d_in[22];
    const float* sinp = (const float*)d_in[23];
    float* out = (float*)d_out;

    float *qkv, *att, *inb, *wqkv, *wo, *bias;
    cudaGetSymbolAddress((void**)&qkv,  g_qkv);
    cudaGetSymbolAddress((void**)&att,  g_att);
    cudaGetSymbolAddress((void**)&inb,  g_in);
    cudaGetSymbolAddress((void**)&wqkv, g_wqkv);
    cudaGetSymbolAddress((void**)&wo,   g_wo);
    cudaGetSymbolAddress((void**)&bias, g_bias);

    cudaFuncSetAttribute(gemm_pipe,   cudaFuncAttributeMaxDynamicSharedMemorySize, GEMM_SMEM);
    cudaFuncSetAttribute(attn_kernel, cudaFuncAttributeMaxDynamicSharedMemorySize, ATT_SMEM);

    // Pre-round everything to tf32
    round_copy<<<8192, 256>>>(inb,                 und,  4096 * 512);
    round_copy<<<8192, 256>>>(inb + 4096 * 2048,   gen,  4096 * 512);
    round_copy<<<4096, 256>>>(wo,                  o_w,  2048 * 512);
    round_copy<<<4096, 256>>>(wo + 2048 * 2048,    o_wg, 2048 * 512);
    assemble_qkv_w<<<6144, 256>>>(wqkv,               q_w,  k_w,  v_w);
    assemble_qkv_w<<<6144, 256>>>(wqkv + 3072 * 2048, q_wg, k_wg, v_wg);
    assemble_bias<<<24, 256>>>(bias, q_b, k_b, v_b, q_bg, k_bg, v_bg);

    // Fused QKV projections, und+gen via z. V columns (>=2560) pre-rounded.
    gemm_pipe<<<dim3(24, 16, 2), 256, GEMM_SMEM>>>(
        inb, (size_t)4096 * 2048, 0, 0, 1,
        wqkv, (size_t)3072 * 2048,
        bias, 3072,
        qkv, 0, 3072, 0, 1, 2,
        2560);

    // RMSNorm + RoPE (rounds q,k outputs)
    norm_rope<<<20480, 256>>>(qkv, cosp, sinp, qn, qng, kn, kng);

    // Flash attention (writes rounded output)
    attn_kernel<<<dim3(16, 4, 16), 256, ATT_SMEM>>>(qkv, att);

    // Output projections, und+gen via z
    gemm_pipe<<<dim3(16, 16, 2), 256, GEMM_SMEM>>>(
        att, 0, 0, 1, 2,
        wo, (size_t)2048 * 2048,
        nullptr, 0,
        out, (size_t)4096 * 2048, 2048, 0, 0, 1,
        1 << 30);
}

// round 12
// speedup vs baseline: 1.6838x; 1.0309x over previous
#include <cuda_runtime.h>
#include <cuda_bf16.h>

// Problem constants
#define S_TOT 8192
#define HID   2048

// Scratch (allocation-free rule: __device__ globals) — all tf32-pre-rounded f32.
// g_in / g_wqkv / g_wo / g_att are K-PAIR-PERMUTED: each 8-word K-group stored
// as [k0,k4,k1,k5,k2,k6,k3,k7] so mma fragment pairs (tig, tig+4) are adjacent.
__device__ float g_qkv [S_TOT * 3072];      // [S][ q | k | v ]  (natural layout)
__device__ float g_att [S_TOT * 2048];      // attention output (rounded, K-permuted)
__device__ float g_in  [S_TOT * 2048];      // rounded inputs (K-permuted); und 0..4095, gen 4096..
__device__ float g_wqkv[2 * 3072 * 2048];   // fused rounded [qw|kw|vw] (K-permuted) und, gen
__device__ float g_wo  [2 * 2048 * 2048];   // rounded o_w (K-permuted) und, gen
__device__ float g_bias[2 * 3072];          // fused bias und, gen

__device__ __forceinline__ unsigned f2t(float f) {
    unsigned u;
    asm("cvt.rna.tf32.f32 %0, %1;" : "=r"(u) : "f"(f));
    return u;
}

__device__ __forceinline__ void mma8(float c[4], const unsigned a[4], unsigned b0, unsigned b1) {
    asm volatile(
        "mma.sync.aligned.m16n8k8.row.col.f32.tf32.tf32.f32 "
        "{%0,%1,%2,%3}, {%4,%5,%6,%7}, {%8,%9}, {%0,%1,%2,%3};"
        : "+f"(c[0]), "+f"(c[1]), "+f"(c[2]), "+f"(c[3])
        : "r"(a[0]), "r"(a[1]), "r"(a[2]), "r"(a[3]), "r"(b0), "r"(b1));
}

__device__ __forceinline__ void cp16(unsigned saddr, const void* g) {
    asm volatile("cp.async.cg.shared.global [%0], [%1], 16;\n" :: "r"(saddr), "l"(g));
}

// ---------------------------------------------------------------------------
// Prep kernels. round_copy8 / assemble_qkv_w8 write the K-pair-permuted layout:
// out 8-group = [k0,k4,k1,k5,k2,k6,k3,k7].
// ---------------------------------------------------------------------------
__global__ void round_copy8(float* __restrict__ dst, const float* __restrict__ src, int n8) {
    int i = blockIdx.x * blockDim.x + threadIdx.x;
    if (i >= n8) return;
    float4 a = ((const float4*)src)[2 * i];
    float4 b = ((const float4*)src)[2 * i + 1];
    ((uint4*)dst)[2 * i]     = make_uint4(f2t(a.x), f2t(b.x), f2t(a.y), f2t(b.y));
    ((uint4*)dst)[2 * i + 1] = make_uint4(f2t(a.z), f2t(b.z), f2t(a.w), f2t(b.w));
}

__global__ void assemble_qkv_w8(float* __restrict__ dst,
                                const float* __restrict__ qw,
                                const float* __restrict__ kw,
                                const float* __restrict__ vw) {
    int i = blockIdx.x * blockDim.x + threadIdx.x;   // 8-group index over 3072x2048
    if (i >= 3072 * 256) return;
    int pos = i * 8;
    int n = pos >> 11, k = pos & 2047;
    const float* src;
    if (n < 2048)      src = qw + (size_t)n * 2048;
    else if (n < 2560) src = kw + (size_t)(n - 2048) * 2048;
    else               src = vw + (size_t)(n - 2560) * 2048;
    float4 a = *(const float4*)(src + k);
    float4 b = *(const float4*)(src + k + 4);
    ((uint4*)dst)[2 * i]     = make_uint4(f2t(a.x), f2t(b.x), f2t(a.y), f2t(b.y));
    ((uint4*)dst)[2 * i + 1] = make_uint4(f2t(a.z), f2t(b.z), f2t(a.w), f2t(b.w));
}

__global__ void assemble_bias(float* __restrict__ dst,
                              const float* qb,  const float* kb,  const float* vb,
                              const float* qbg, const float* kbg, const float* vbg) {
    int i = blockIdx.x * blockDim.x + threadIdx.x;   // 0..6143
    if (i >= 6144) return;
    bool gsel = i >= 3072;
    int n = gsel ? i - 3072 : i;
    const float* q = gsel ? qbg : qb;
    const float* k = gsel ? kbg : kb;
    const float* v = gsel ? vbg : vb;
    dst[i] = (n < 2048) ? q[n] : (n < 2560) ? k[n - 2048] : v[n - 2560];
}

// ---------------------------------------------------------------------------
// Pipelined tf32 GEMM on K-permuted operands.
// 256 threads, 8 warps (4m x 2n), warp tile 64x64. CTA tile 256x128, K-chunk 64,
// 2-stage ring. ROW_W=72 (mod 32 == 8): LDS.64 fragment loads are conflict-free.
// Explicit двойной-buffered fragment registers across ks steps.
// ---------------------------------------------------------------------------
#define ROW_W   72
#define STG_W   ((256 + 128) * ROW_W)        // 27648 words/stage
#define GEMM_SMEM (2 * STG_W * 4)            // 221,184 B

__global__ __launch_bounds__(256, 1) void gemm_pipe(
    const float* __restrict__ A, size_t az, int a_off0, int a_step, int a_stride,
    const float* __restrict__ W, size_t wz,
    const float* __restrict__ bias, size_t bz,
    float* __restrict__ C, size_t cz, int ldc, int c_off0, int c_step, int c_stride,
    int round_from)
{
    extern __shared__ unsigned gsm[];
    const int tid = threadIdx.x;
    const int wid = tid >> 5, lane = tid & 31;
    const int gid = lane >> 2, tig = lane & 3;
    const int wm = (wid & 3) * 64, wn = (wid >> 2) * 64;
    const int bm = blockIdx.y * 256, bn = blockIdx.x * 128;
    const int z = blockIdx.z;

    A += (size_t)z * az;
    W += (size_t)z * wz;
    if (bias) bias += (size_t)z * bz;
    C += (size_t)z * cz;
    const int a_off = a_off0 + z * a_step;
    const int c_off = c_off0 + z * c_step;

    // loaders: thread moves 16 x 16B for A, 8 x 16B for B per stage
    const int lr  = tid >> 3;           // 0..31
    const int lc  = (tid & 7) * 4;      // word col within first 32-half
    const float* ga[8];
    const float* gw[4];
    unsigned offA[8], offB[4];
#pragma unroll
    for (int i = 0; i < 8; i++) {
        int r = lr + 32 * i;            // 0..255
        ga[i]   = A + (size_t)(a_off + (bm + r) * a_stride) * 2048 + lc;
        offA[i] = (r * ROW_W + lc) * 4;
    }
#pragma unroll
    for (int i = 0; i < 4; i++) {
        int r = lr + 32 * i;            // 0..127
        gw[i]   = W + (size_t)(bn + r) * 2048 + lc;
        offB[i] = ((256 + r) * ROW_W + lc) * 4;
    }
    const unsigned sbase = (unsigned)__cvta_generic_to_shared(gsm);

#define LOADCHUNK(slot, kc) do {                                                       \
    unsigned b_ = sbase + (slot) * (STG_W * 4);                                        \
    int kk_ = (kc) * 64;                                                               \
    _Pragma("unroll") for (int i_ = 0; i_ < 8; i_++) {                                 \
        cp16(b_ + offA[i_],       ga[i_] + kk_);                                       \
        cp16(b_ + offA[i_] + 128, ga[i_] + kk_ + 32);                                  \
    }                                                                                  \
    _Pragma("unroll") for (int i_ = 0; i_ < 4; i_++) {                                 \
        cp16(b_ + offB[i_],       gw[i_] + kk_);                                       \
        cp16(b_ + offB[i_] + 128, gw[i_] + kk_ + 32);                                  \
    }                                                                                  \
    asm volatile("cp.async.commit_group;\n" ::);                                       \
} while (0)

// fragment load for one ks step into buffer `buf` (LDS.64, conflict-free)
#define LOADFRAG(buf, ks) do {                                                         \
    _Pragma("unroll") for (int mf_ = 0; mf_ < 4; mf_++) {                              \
        uint2 u0_ = *(const uint2*)&sA[(wm + mf_ * 16 + gid)     * ROW_W + (ks) * 8 + 2 * tig]; \
        uint2 u1_ = *(const uint2*)&sA[(wm + mf_ * 16 + gid + 8) * ROW_W + (ks) * 8 + 2 * tig]; \
        af[buf][mf_][0] = u0_.x; af[buf][mf_][2] = u0_.y;                              \
        af[buf][mf_][1] = u1_.x; af[buf][mf_][3] = u1_.y;                              \
    }                                                                                  \
    _Pragma("unroll") for (int nf_ = 0; nf_ < 8; nf_++) {                              \
        uint2 v_ = *(const uint2*)&sB[(wn + nf_ * 8 + gid) * ROW_W + (ks) * 8 + 2 * tig]; \
        bf[buf][nf_][0] = v_.x; bf[buf][nf_][1] = v_.y;                                \
    }                                                                                  \
} while (0)

    float acc[4][8][4];
#pragma unroll
    for (int i = 0; i < 4; i++)
#pragma unroll
        for (int j = 0; j < 8; j++)
#pragma unroll
            for (int c = 0; c < 4; c++) acc[i][j][c] = 0.f;

    LOADCHUNK(0, 0);
    LOADCHUNK(1, 1);

#pragma unroll 1
    for (int c = 0; c < 32; c++) {
        const int slot = c & 1;
        if (c < 31) asm volatile("cp.async.wait_group 1;\n" ::);
        else        asm volatile("cp.async.wait_group 0;\n" ::);
        __syncthreads();

        const unsigned* sA = gsm + slot * STG_W;
        const unsigned* sB = sA + 256 * ROW_W;

        unsigned af[2][4][4], bf[2][8][2];
        LOADFRAG(0, 0);
#pragma unroll
        for (int ks = 0; ks < 8; ks++) {
            const int cur = ks & 1;
            if (ks < 7) LOADFRAG(cur ^ 1, ks + 1);
#pragma unroll
            for (int mf = 0; mf < 4; mf++)
#pragma unroll
                for (int nf = 0; nf < 8; nf++)
                    mma8(acc[mf][nf], af[cur][mf], bf[cur][nf][0], bf[cur][nf][1]);
        }

        if (c + 2 < 32) {
            __syncthreads();               // all warps done reading this slot
            LOADCHUNK(slot, c + 2);        // overlaps compute of chunk c+1
        }
    }
#undef LOADCHUNK
#undef LOADFRAG

#pragma unroll
    for (int mf = 0; mf < 4; mf++) {
#pragma unroll
        for (int nf = 0; nf < 8; nf++) {
            int gc = bn + wn + nf * 8 + tig * 2;
            float b0 = bias ? __ldg(bias + gc)     : 0.f;
            float b1 = bias ? __ldg(bias + gc + 1) : 0.f;
            int gr = bm + wm + mf * 16 + gid;
            float v00 = acc[mf][nf][0] + b0, v01 = acc[mf][nf][1] + b1;
            float v10 = acc[mf][nf][2] + b0, v11 = acc[mf][nf][3] + b1;
            if (gc >= round_from) {
                v00 = __uint_as_float(f2t(v00)); v01 = __uint_as_float(f2t(v01));
                v10 = __uint_as_float(f2t(v10)); v11 = __uint_as_float(f2t(v11));
            }
            *(float2*)&C[(size_t)(c_off + gr * c_stride) * ldc + gc]       = make_float2(v00, v01);
            *(float2*)&C[(size_t)(c_off + (gr + 8) * c_stride) * ldc + gc] = make_float2(v10, v11);
        }
    }
}

// ---------------------------------------------------------------------------
// Per-head RMSNorm + RoPE, in-place on g_qkv; outputs tf32-ROUNDED.
// ---------------------------------------------------------------------------
__global__ __launch_bounds__(256) void norm_rope(
    float* __restrict__ qkv,
    const float* __restrict__ cosp, const float* __restrict__ sinp,
    const float* __restrict__ qn, const float* __restrict__ qng,
    const float* __restrict__ kn, const float* __restrict__ kng)
{
    int task = blockIdx.x * 8 + (threadIdx.x >> 5);
    int lane = threadIdx.x & 31;
    int s = task / 20, j = task % 20;
    bool und = (s & 1) == 0;
    const float* w;
    int off;
    if (j < 16) { off = j * 128;               w = und ? qn : qng; }
    else        { off = 2048 + (j - 16) * 128; w = und ? kn : kng; }

    float* p = qkv + (size_t)s * 3072 + off;
    float x0 = p[lane], x1 = p[lane + 32], x2 = p[lane + 64], x3 = p[lane + 96];
    float ss = x0 * x0 + x1 * x1 + x2 * x2 + x3 * x3;
#pragma unroll
    for (int d = 16; d; d >>= 1) ss += __shfl_xor_sync(0xffffffffu, ss, d);
    float r = rsqrtf(ss * (1.0f / 128.0f) + 1e-6f);
    x0 = x0 * r * w[lane];      x1 = x1 * r * w[lane + 32];
    x2 = x2 * r * w[lane + 64]; x3 = x3 * r * w[lane + 96];

    const float* cs = cosp + (size_t)s * 128;
    const float* sn = sinp + (size_t)s * 128;
    float c0 = cs[lane], c1 = cs[lane + 32], c2 = cs[lane + 64], c3 = cs[lane + 96];
    float s0 = sn[lane], s1 = sn[lane + 32], s2 = sn[lane + 64], s3 = sn[lane + 96];

    p[lane]      = __uint_as_float(f2t(x0 * c0 - x2 * s0));
    p[lane + 32] = __uint_as_float(f2t(x1 * c1 - x3 * s1));
    p[lane + 64] = __uint_as_float(f2t(x2 * c2 + x0 * s2));
    p[lane + 96] = __uint_as_float(f2t(x3 * c3 + x1 * s3));
}

// ---------------------------------------------------------------------------
// Causal GQA flash attention (tf32 mma). K/V pre-rounded -> raw cp.async fill.
// Output written K-pair-PERMUTED (consumed by o-proj GEMM).
// ---------------------------------------------------------------------------
#define SK_STR 132
#define SV_STR 136
#define SP_STR 68
#define KV_W   (64 * SK_STR + 64 * SV_STR)
#define ATT_SMEM ((KV_W + 8 * 16 * SP_STR) * 4)

__global__ __launch_bounds__(256, 1) void attn_kernel(
    const float* __restrict__ qkv, float* __restrict__ outp)
{
    extern __shared__ unsigned sm[];
    unsigned* sK = sm;
    unsigned* sV = sm + 64 * SK_STR;
    float* sP = (float*)(sm + KV_W);

    const int qt = blockIdx.x, hkv = blockIdx.y, b = blockIdx.z;
    const int tid = threadIdx.x, wid = tid >> 5, lane = tid & 31;
    const int gid = lane >> 2, tig = lane & 3;
    const int g = wid >> 1;
    const int h = hkv * 4 + g;
    const int q0 = qt * 32;
    const int qrow = q0 + (wid & 1) * 16 + gid;
    const int trow = b * 512 + qrow;
    const float scale = 0.08838834764831845f;

    unsigned qa[16][4];
    {
        const float* qp  = qkv + (size_t)trow * 3072 + h * 128;
        const float* qp8 = qp + 8 * 3072;
#pragma unroll
        for (int kf = 0; kf < 16; kf++) {
            qa[kf][0] = __float_as_uint(qp [kf * 8 + tig]);
            qa[kf][2] = __float_as_uint(qp [kf * 8 + tig + 4]);
            qa[kf][1] = __float_as_uint(qp8[kf * 8 + tig]);
            qa[kf][3] = __float_as_uint(qp8[kf * 8 + tig + 4]);
        }
    }

    const unsigned sb = (unsigned)__cvta_generic_to_shared(sm);
    const int krow = tid >> 2;
    const int kcb  = (tid & 3) * 32;

    float o[16][4];
#pragma unroll
    for (int i = 0; i < 16; i++)
#pragma unroll
        for (int c = 0; c < 4; c++) o[i][c] = 0.f;
    float m0 = -1e30f, m1 = -1e30f, l0 = 0.f, l1 = 0.f;
    float* myP = sP + wid * 16 * SP_STR;
    const int ntiles = (q0 >> 6) + 1;

#pragma unroll 1
    for (int j = 0; j < ntiles; j++) {
        int c0 = j * 64;
        __syncthreads();
        {
            const float* kb = qkv + (size_t)(b * 512 + c0 + krow) * 3072 + 2048 + hkv * 128 + kcb;
            const float* vb = kb + 512;
#pragma unroll
            for (int t = 0; t < 8; t++) {
                cp16(sb + (krow * SK_STR + kcb + t * 4) * 4, kb + t * 4);
                cp16(sb + (64 * SK_STR + krow * SV_STR + kcb + t * 4) * 4, vb + t * 4);
            }
            asm volatile("cp.async.commit_group;\n" ::);
            asm volatile("cp.async.wait_group 0;\n" ::);
        }
        __syncthreads();

        float s[8][4];
#pragma unroll
        for (int nf = 0; nf < 8; nf++)
#pragma unroll
            for (int c = 0; c < 4; c++) s[nf][c] = 0.f;

#pragma unroll
        for (int kf = 0; kf < 16; kf++) {
#pragma unroll
            for (int nf = 0; nf < 8; nf++) {
                unsigned b0 = sK[(nf * 8 + gid) * SK_STR + kf * 8 + tig];
                unsigned b1 = sK[(nf * 8 + gid) * SK_STR + kf * 8 + tig + 4];
                mma8(s[nf], qa[kf], b0, b1);
            }
        }

#pragma unroll
        for (int nf = 0; nf < 8; nf++)
#pragma unroll
            for (int c = 0; c < 4; c++) s[nf][c] *= scale;

        if (j == ntiles - 1) {
#pragma unroll
            for (int nf = 0; nf < 8; nf++) {
                int col = c0 + nf * 8 + tig * 2;
                if (col     > qrow)     s[nf][0] = -1e30f;
                if (col + 1 > qrow)     s[nf][1] = -1e30f;
                if (col     > qrow + 8) s[nf][2] = -1e30f;
                if (col + 1 > qrow + 8) s[nf][3] = -1e30f;
            }
        }

        float mj0 = -1e30f, mj1 = -1e30f;
#pragma unroll
        for (int nf = 0; nf < 8; nf++) {
            mj0 = fmaxf(mj0, fmaxf(s[nf][0], s[nf][1]));
            mj1 = fmaxf(mj1, fmaxf(s[nf][2], s[nf][3]));
        }
        mj0 = fmaxf(mj0, __shfl_xor_sync(0xffffffffu, mj0, 1));
        mj0 = fmaxf(mj0, __shfl_xor_sync(0xffffffffu, mj0, 2));
        mj1 = fmaxf(mj1, __shfl_xor_sync(0xffffffffu, mj1, 1));
        mj1 = fmaxf(mj1, __shfl_xor_sync(0xffffffffu, mj1, 2));

        float mn0 = fmaxf(m0, mj0), mn1 = fmaxf(m1, mj1);
        float f0 = __expf(m0 - mn0), f1 = __expf(m1 - mn1);
        m0 = mn0; m1 = mn1;
        l0 *= f0; l1 *= f1;
#pragma unroll
        for (int nf = 0; nf < 16; nf++) {
            o[nf][0] *= f0; o[nf][1] *= f0;
            o[nf][2] *= f1; o[nf][3] *= f1;
        }
#pragma unroll
        for (int nf = 0; nf < 8; nf++) {
            float p0 = __expf(s[nf][0] - m0), p1 = __expf(s[nf][1] - m0);
            float p2 = __expf(s[nf][2] - m1), p3 = __expf(s[nf][3] - m1);
            l0 += p0 + p1; l1 += p2 + p3;
            *(float2*)&myP[gid * SP_STR + nf * 8 + tig * 2]       = make_float2(p0, p1);
            *(float2*)&myP[(gid + 8) * SP_STR + nf * 8 + tig * 2] = make_float2(p2, p3);
        }
        __syncwarp();
#pragma unroll
        for (int kf = 0; kf < 8; kf++) {
            unsigned a[4];
            a[0] = f2t(myP[gid * SP_STR + kf * 8 + tig]);
            a[2] = f2t(myP[gid * SP_STR + kf * 8 + tig + 4]);
            a[1] = f2t(myP[(gid + 8) * SP_STR + kf * 8 + tig]);
            a[3] = f2t(myP[(gid + 8) * SP_STR + kf * 8 + tig + 4]);
#pragma unroll
            for (int nf = 0; nf < 16; nf++) {
                unsigned b0 = sV[(kf * 8 + tig) * SV_STR + nf * 8 + gid];
                unsigned b1 = sV[(kf * 8 + tig + 4) * SV_STR + nf * 8 + gid];
                mma8(o[nf], a, b0, b1);
            }
        }
        __syncwarp();
    }

    float L0 = l0 + __shfl_xor_sync(0xffffffffu, l0, 1);
    L0 += __shfl_xor_sync(0xffffffffu, L0, 2);
    float L1 = l1 + __shfl_xor_sync(0xffffffffu, l1, 1);
    L1 += __shfl_xor_sync(0xffffffffu, L1, 2);
    float inv0 = 1.f / L0, inv1 = 1.f / L1;

    // K-pair-permuted, tf32-rounded output (cols 2t,2t+1 -> positions p, p+2)
    float* op  = outp + (size_t)trow * 2048 + h * 128;
    float* op8 = op + 8 * 2048;
    const int p = ((tig & 1) << 2) | (tig >> 1);
#pragma unroll
    for (int nf = 0; nf < 16; nf++) {
        int g0 = nf * 8;
        op [g0 + p]     = __uint_as_float(f2t(o[nf][0] * inv0));
        op [g0 + p + 2] = __uint_as_float(f2t(o[nf][1] * inv0));
        op8[g0 + p]     = __uint_as_float(f2t(o[nf][2] * inv1));
        op8[g0 + p + 2] = __uint_as_float(f2t(o[nf][3] * inv1));
    }
}

// ---------------------------------------------------------------------------
extern "C" void kernel_launch(void* const* d_in, const int* in_sizes, int n_in,
                              void* d_out, int out_size)
{
    const float* und  = (const float*)d_in[0];
    const float* gen  = (const float*)d_in[1];
    const float* q_w  = (const float*)d_in[4];
    const float* q_b  = (const float*)d_in[5];
    const float* k_w  = (const float*)d_in[6];
    const float* k_b  = (const float*)d_in[7];
    const float* v_w  = (const float*)d_in[8];
    const float* v_b  = (const float*)d_in[9];
    const float* o_w  = (const float*)d_in[10];
    const float* q_wg = (const float*)d_in[11];
    const float* q_bg = (const float*)d_in[12];
    const float* k_wg = (const float*)d_in[13];
    const float* k_bg = (const float*)d_in[14];
    const float* v_wg = (const float*)d_in[15];
    const float* v_bg = (const float*)d_in[16];
    const float* o_wg = (const float*)d_in[17];
    const float* qn   = (const float*)d_in[18];
    const float* kn   = (const float*)d_in[19];
    const float* qng  = (const float*)d_in[20];
    const float* kng  = (const float*)d_in[21];
    const float* cosp = (const float*)d_in[22];
    const float* sinp = (const float*)d_in[23];
    float* out = (float*)d_out;

    float *qkv, *att, *inb, *wqkv, *wo, *bias;
    cudaGetSymbolAddress((void**)&qkv,  g_qkv);
    cudaGetSymbolAddress((void**)&att,  g_att);
    cudaGetSymbolAddress((void**)&inb,  g_in);
    cudaGetSymbolAddress((void**)&wqkv, g_wqkv);
    cudaGetSymbolAddress((void**)&wo,   g_wo);
    cudaGetSymbolAddress((void**)&bias, g_bias);

    cudaFuncSetAttribute(gemm_pipe,   cudaFuncAttributeMaxDynamicSharedMemorySize, GEMM_SMEM);
    cudaFuncSetAttribute(attn_kernel, cudaFuncAttributeMaxDynamicSharedMemorySize, ATT_SMEM);

    // Pre-round + K-pair-permute inputs/weights
    round_copy8<<<4096, 256>>>(inb,                 und,  4096 * 256);
    round_copy8<<<4096, 256>>>(inb + 4096 * 2048,   gen,  4096 * 256);
    round_copy8<<<2048, 256>>>(wo,                  o_w,  2048 * 256);
    round_copy8<<<2048, 256>>>(wo + 2048 * 2048,    o_wg, 2048 * 256);
    assemble_qkv_w8<<<3072, 256>>>(wqkv,               q_w,  k_w,  v_w);
    assemble_qkv_w8<<<3072, 256>>>(wqkv + 3072 * 2048, q_wg, k_wg, v_wg);
    assemble_bias<<<24, 256>>>(bias, q_b, k_b, v_b, q_bg, k_bg, v_bg);

    // Fused QKV projections, und+gen via z. V columns (>=2560) pre-rounded.
    gemm_pipe<<<dim3(24, 16, 2), 256, GEMM_SMEM>>>(
        inb, (size_t)4096 * 2048, 0, 0, 1,
        wqkv, (size_t)3072 * 2048,
        bias, 3072,
        qkv, 0, 3072, 0, 1, 2,
        2560);

    // RMSNorm + RoPE (rounds q,k outputs)
    norm_rope<<<20480, 256>>>(qkv, cosp, sinp, qn, qng, kn, kng);

    // Flash attention (writes rounded, K-permuted output)
    attn_kernel<<<dim3(16, 4, 16), 256, ATT_SMEM>>>(qkv, att);

    // Output projections, und+gen via z
    gemm_pipe<<<dim3(16, 16, 2), 256, GEMM_SMEM>>>(
        att, 0, 0, 1, 2,
        wo, (size_t)2048 * 2048,
        nullptr, 0,
        out, (size_t)4096 * 2048, 2048, 0, 0, 1,
        1 << 30);
}